// round 3
// baseline (speedup 1.0000x reference)
#include <cuda_runtime.h>
#include <math.h>

// B=2, D=H=W=128, C=4 image; label int32 C=1; coarse flow [2,4,4,4,3].
// Output: image [2,128,128,128,4] f32 then label [2,128,128,128] (as float).

#define NVOX      (2*128*128*128)
#define IMG_ELEMS (NVOX*4)
#define FLOW_N    (NVOX*3)          // 12,582,912 floats per flow buffer

__device__ float d_W[128][4];       // fp32 resize weights (jax-faithful rounding)
__device__ float d_G[16];           // fp32 gaussian taps (float64 -> f32, numpy-faithful)
__device__ float d_A1[2*128*4*4*3];      // resize-D intermediate
__device__ float d_A2[2*128*128*4*3];    // resize-H intermediate
__device__ float d_B1[FLOW_N];           // ping
__device__ float d_B2[FLOW_N];           // pong

// ---- stage 0: weights, computed with the exact op structure jax/numpy use ----
__device__ __forceinline__ float keys_f32(float x) {
    // ((1.5*x - 2.5)*x)*x + 1  /  ((-0.5*x + 2.5)*x - 4)*x + 2, separate mul/add (no fma)
    if (x < 1.0f) {
        float t = __fadd_rn(__fmul_rn(1.5f, x), -2.5f);
        t = __fmul_rn(t, x); t = __fmul_rn(t, x);
        return __fadd_rn(t, 1.0f);
    }
    if (x < 2.0f) {
        float t = __fadd_rn(__fmul_rn(-0.5f, x), 2.5f);
        t = __fadd_rn(__fmul_rn(t, x), -4.0f);
        t = __fmul_rn(t, x);
        return __fadd_rn(t, 2.0f);
    }
    return 0.0f;
}

__global__ void init_weights_kernel() {
    int x = threadIdx.x; // 0..127
    // sample_f = (x+0.5)/32 - 0.5 (all steps exact in f32)
    float s = __fadd_rn(__fdiv_rn(__fadd_rn((float)x, 0.5f), 32.0f), -0.5f);
    float wv[4];
#pragma unroll
    for (int a = 0; a < 4; a++) wv[a] = keys_f32(fabsf(__fadd_rn(s, -(float)a)));
    float tot = __fadd_rn(__fadd_rn(__fadd_rn(wv[0], wv[1]), wv[2]), wv[3]);
#pragma unroll
    for (int a = 0; a < 4; a++) d_W[x][a] = __fdiv_rn(wv[a], tot);

    if (x < 16) {
        // numpy float64: k = exp(-ax^2/12.5); k /= k.sum(); then cast f32
        double gs = 0.0;
        for (int j = 0; j < 16; j++) { double o = (double)(j - 7); gs += exp(-o * o / 12.5); }
        double o = (double)(x - 7);
        d_G[x] = (float)(exp(-o * o / 12.5) / gs);
    }
}

// ---- stage 1a: resize D.  A1[b][d][bb][e][c] = sum_a W[d][a]*coarse[b][a][bb][e][c]
__global__ void resizeD_kernel(const float* __restrict__ coarse) {
    int i = blockIdx.x * blockDim.x + threadIdx.x; // 2*128*48 = 12288
    if (i >= 2 * 128 * 48) return;
    int c48 = i % 48, d = (i / 48) % 128, b = i / (48 * 128);
    const float* cf = coarse + b * 192;
    float acc = 0.0f;
#pragma unroll
    for (int a = 0; a < 4; a++) acc = fmaf(d_W[d][a], cf[a * 48 + c48], acc);
    d_A1[i] = acc;
}

// ---- stage 1b: resize H.  A2[b][d][h][e][c] = sum_bb W[h][bb]*A1[b][d][bb][e][c]
__global__ void resizeH_kernel() {
    int i = blockIdx.x * blockDim.x + threadIdx.x; // 2*128*128*12 = 393216
    if (i >= 2 * 128 * 128 * 12) return;
    int ec = i % 12, h = (i / 12) % 128, d = (i / (12 * 128)) % 128, b = i / (12 * 128 * 128);
    const float* a1 = d_A1 + (b * 128 + d) * 48;
    float acc = 0.0f;
#pragma unroll
    for (int bb = 0; bb < 4; bb++) acc = fmaf(d_W[h][bb], a1[bb * 12 + ec], acc);
    d_A2[i] = acc;
}

// ---- stage 2: resize W.  B1[b][d][h][w][c] = sum_e W[w][e]*A2[b][d][h][e][c]
__global__ __launch_bounds__(384) void resizeW_kernel() {
    __shared__ float a2s[12];
    int t = threadIdx.x;                 // 0..383 -> (w = t/3, c = t%3)
    int h = blockIdx.x, d = blockIdx.y, b = blockIdx.z;
    if (t < 12) a2s[t] = d_A2[((b * 128 + d) * 128 + h) * 12 + t];
    __syncthreads();
    int w = t / 3, c = t - 3 * w;
    float acc = 0.0f;
#pragma unroll
    for (int e = 0; e < 4; e++) acc = fmaf(d_W[w][e], a2s[e * 3 + c], acc);
    d_B1[(((b * 128 + d) * 128 + h) * 128) * 3 + t] = acc;
}

// ---- gaussian conv along D: out[d] = sum_j k[j]*in[d+j-7] (zero outside) ----
__global__ __launch_bounds__(256) void convD_kernel(const float* __restrict__ in, float* __restrict__ outp) {
    __shared__ float tile[128][32];
    int tx = threadIdx.x, ty = threadIdx.y;        // (32, 8)
    int wc0 = blockIdx.x * 32;                     // 12 tiles of 384
    int h = blockIdx.y, b = blockIdx.z;
    size_t base = ((size_t)b * 128 * 128 + h) * 384 + wc0; // + d*128*384
    for (int dd = ty; dd < 128; dd += 8)
        tile[dd][tx] = in[base + (size_t)dd * 128 * 384 + tx];
    __syncthreads();
    for (int dd = ty; dd < 128; dd += 8) {
        float acc = 0.0f;
#pragma unroll
        for (int j = 0; j < 16; j++) {
            int s = dd + j - 7;
            if (s >= 0 && s < 128) acc = fmaf(d_G[j], tile[s][tx], acc);
        }
        outp[base + (size_t)dd * 128 * 384 + tx] = acc;
    }
}

// ---- gaussian conv along H ----
__global__ __launch_bounds__(256) void convH_kernel(const float* __restrict__ in, float* __restrict__ outp) {
    __shared__ float tile[128][32];
    int tx = threadIdx.x, ty = threadIdx.y;
    int wc0 = blockIdx.x * 32;
    int d = blockIdx.y, b = blockIdx.z;
    size_t base = ((size_t)b * 128 + d) * 128 * 384 + wc0; // + h*384
    for (int hh = ty; hh < 128; hh += 8)
        tile[hh][tx] = in[base + (size_t)hh * 384 + tx];
    __syncthreads();
    for (int hh = ty; hh < 128; hh += 8) {
        float acc = 0.0f;
#pragma unroll
        for (int j = 0; j < 16; j++) {
            int s = hh + j - 7;
            if (s >= 0 && s < 128) acc = fmaf(d_G[j], tile[s][tx], acc);
        }
        outp[base + (size_t)hh * 384 + tx] = acc;
    }
}

// ---- gaussian conv along W ----
__global__ __launch_bounds__(384) void convW_kernel(const float* __restrict__ in, float* __restrict__ outp) {
    __shared__ float row[384];
    int t = threadIdx.x;
    int h = blockIdx.x, d = blockIdx.y, b = blockIdx.z;
    size_t base = (((size_t)b * 128 + d) * 128 + h) * 384;
    row[t] = in[base + t];
    __syncthreads();
    int w = t / 3, c = t - 3 * w;
    float acc = 0.0f;
#pragma unroll
    for (int j = 0; j < 16; j++) {
        int s = w + j - 7;
        if (s >= 0 && s < 128) acc = fmaf(d_G[j], row[s * 3 + c], acc);
    }
    outp[base + t] = acc;
}

// ---- final: warp image (trilinear) + label (nearest), flow from d_B2 ----
__device__ __forceinline__ float4 lerp4(float4 p, float4 q, float t) {
    float4 r;
    r.x = fmaf(t, q.x - p.x, p.x);
    r.y = fmaf(t, q.y - p.y, p.y);
    r.z = fmaf(t, q.z - p.z, p.z);
    r.w = fmaf(t, q.w - p.w, p.w);
    return r;
}

__global__ __launch_bounds__(128) void warp_kernel(
    const float* __restrict__ img, const int* __restrict__ lab, float* __restrict__ out)
{
    const int w = threadIdx.x;
    const int h = blockIdx.x, d = blockIdx.y, b = blockIdx.z;
    const int bbase = b << 21;
    const int oidx = bbase + (d * 128 + h) * 128 + w;

    // flow * ALPHA (rounded), then grid + flow (rounded) — matches reference op order
    const float fd = __fmul_rn(d_B2[(size_t)oidx * 3 + 0], 35.0f);
    const float fh = __fmul_rn(d_B2[(size_t)oidx * 3 + 1], 35.0f);
    const float fw = __fmul_rn(d_B2[(size_t)oidx * 3 + 2], 35.0f);
    const float wd = __fadd_rn((float)d, fd);
    const float wh = __fadd_rn((float)h, fh);
    const float ww = __fadd_rn((float)w, fw);

    const float fld = floorf(wd), flh = floorf(wh), flw = floorf(ww);
    const float td = wd - fld, th = wh - flh, tw = ww - flw;

    const int id = (int)fld, ih = (int)flh, iw = (int)flw;
    const int d0 = min(max(id,     0), 127), d1 = min(max(id + 1, 0), 127);
    const int h0 = min(max(ih,     0), 127), h1 = min(max(ih + 1, 0), 127);
    const int w0 = min(max(iw,     0), 127), w1 = min(max(iw + 1, 0), 127);

    const float4* __restrict__ I = reinterpret_cast<const float4*>(img);
    const int r00 = bbase + (d0 * 128 + h0) * 128;
    const int r01 = bbase + (d0 * 128 + h1) * 128;
    const int r10 = bbase + (d1 * 128 + h0) * 128;
    const int r11 = bbase + (d1 * 128 + h1) * 128;

    const float4 a000 = I[r00 + w0], a001 = I[r00 + w1];
    const float4 a010 = I[r01 + w0], a011 = I[r01 + w1];
    const float4 a100 = I[r10 + w0], a101 = I[r10 + w1];
    const float4 a110 = I[r11 + w0], a111 = I[r11 + w1];

    const float4 c00 = lerp4(a000, a001, tw);
    const float4 c01 = lerp4(a010, a011, tw);
    const float4 c10 = lerp4(a100, a101, tw);
    const float4 c11 = lerp4(a110, a111, tw);
    const float4 c0  = lerp4(c00, c01, th);
    const float4 c1  = lerp4(c10, c11, th);
    reinterpret_cast<float4*>(out)[oidx] = lerp4(c0, c1, td);

    // nearest label on the SAME fp32 warp values the reference rounds (half-even)
    const int nd = min(max((int)rintf(wd), 0), 127);
    const int nh = min(max((int)rintf(wh), 0), 127);
    const int nw = min(max((int)rintf(ww), 0), 127);
    out[IMG_ELEMS + oidx] = (float)__ldg(&lab[bbase + (nd * 128 + nh) * 128 + nw]);
}

extern "C" void kernel_launch(void* const* d_in, const int* in_sizes, int n_in,
                              void* d_out, int out_size) {
    const float* img    = (const float*)d_in[0];
    const int*   lab    = (const int*)  d_in[1];
    const float* coarse = (const float*)d_in[2];
    float* out = (float*)d_out;

    float *b1, *b2;
    cudaGetSymbolAddress((void**)&b1, d_B1);
    cudaGetSymbolAddress((void**)&b2, d_B2);

    init_weights_kernel<<<1, 128>>>();
    resizeD_kernel<<<(12288 + 255) / 256, 256>>>(coarse);
    resizeH_kernel<<<(393216 + 255) / 256, 256>>>();
    resizeW_kernel<<<dim3(128, 128, 2), 384>>>();
    convD_kernel<<<dim3(12, 128, 2), dim3(32, 8)>>>(b1, b2);
    convH_kernel<<<dim3(12, 128, 2), dim3(32, 8)>>>(b2, b1);
    convW_kernel<<<dim3(128, 128, 2), 384>>>(b1, b2);
    warp_kernel<<<dim3(128, 128, 2), 128>>>(img, lab, out);
}

// round 4
// speedup vs baseline: 1.4806x; 1.4806x over previous
#include <cuda_runtime.h>
#include <math.h>

// B=2, D=H=W=128, C=4 image; label int32 C=1; coarse flow [2,4,4,4,3].
// Output: image [2,128,128,128,4] f32 then label [2,128,128,128] (as float).

#define NVOX      (2*128*128*128)
#define IMG_ELEMS (NVOX*4)
#define FLOW_N    (NVOX*3)

__device__ float d_W[128][4];   // fp32 resize weights (jax-faithful rounding)
__device__ float d_G[16];       // fp32 gaussian taps (float64 -> f32, numpy-faithful)
__device__ float d_F2[FLOW_N];  // flow after resize + convD   [b][d][h][w*3+c]
__device__ float d_F3[FLOW_N];  // flow after convH            [b][d][h][w*3+c]

// ---------------- stage 0: weights (exact op structure jax/numpy use) ----------------
__device__ __forceinline__ float keys_f32(float x) {
    if (x < 1.0f) {
        float t = __fadd_rn(__fmul_rn(1.5f, x), -2.5f);
        t = __fmul_rn(t, x); t = __fmul_rn(t, x);
        return __fadd_rn(t, 1.0f);
    }
    if (x < 2.0f) {
        float t = __fadd_rn(__fmul_rn(-0.5f, x), 2.5f);
        t = __fadd_rn(__fmul_rn(t, x), -4.0f);
        t = __fmul_rn(t, x);
        return __fadd_rn(t, 2.0f);
    }
    return 0.0f;
}

__global__ void init_weights_kernel() {
    int x = threadIdx.x; // 0..127
    float s = __fadd_rn(__fdiv_rn(__fadd_rn((float)x, 0.5f), 32.0f), -0.5f);
    float wv[4];
#pragma unroll
    for (int a = 0; a < 4; a++) wv[a] = keys_f32(fabsf(__fadd_rn(s, -(float)a)));
    float tot = __fadd_rn(__fadd_rn(__fadd_rn(wv[0], wv[1]), wv[2]), wv[3]);
#pragma unroll
    for (int a = 0; a < 4; a++) d_W[x][a] = __fdiv_rn(wv[a], tot);

    if (x < 16) {
        double gs = 0.0;
        for (int j = 0; j < 16; j++) { double o = (double)(j - 7); gs += exp(-o * o / 12.5); }
        double o = (double)(x - 7);
        d_G[x] = (float)(exp(-o * o / 12.5) / gs);
    }
}

// ---------------- fused resizeD+resizeH+resizeW+convD ----------------
// grid (4, 128, 2) = (d-tile, h, b); 384 threads (wc = w*3+c)
extern __shared__ float dyn_smem[];
__global__ __launch_bounds__(384) void flowD_kernel(const float* __restrict__ coarse) {
    float* B1s = dyn_smem;                  // [48][384]
    __shared__ float cf[192];
    __shared__ float A2h[128 * 12];         // [d'][e*3+c]
    const int t = threadIdx.x;
    const int t0 = blockIdx.x * 32;
    const int h = blockIdx.y, b = blockIdx.z;

    if (t < 192) cf[t] = coarse[b * 192 + t];
    __syncthreads();

    // A2h[d'][ec] = sum_bb W[h][bb] * (sum_a W[d'][a] * cf[a][bb][ec])  (same fma order as staged kernels)
    const float wh0 = d_W[h][0], wh1 = d_W[h][1], wh2 = d_W[h][2], wh3 = d_W[h][3];
    for (int i = t; i < 1536; i += 384) {
        const int dp = i / 12, ec = i - dp * 12;
        float acc = 0.0f;
#pragma unroll
        for (int bb = 0; bb < 4; bb++) {
            float a1 = 0.0f;
#pragma unroll
            for (int a = 0; a < 4; a++)
                a1 = fmaf(d_W[dp][a], cf[a * 48 + bb * 12 + ec], a1);
            const float whb = (bb == 0) ? wh0 : (bb == 1) ? wh1 : (bb == 2) ? wh2 : wh3;
            acc = fmaf(whb, a1, acc);
        }
        A2h[i] = acc;
    }
    __syncthreads();

    // B1 window: d' in [t0-7, t0+40]; zero outside [0,128) (zero-pad == tap-skip, bit-exact)
    const int w = t / 3, c = t - 3 * w;
    const float ww0 = d_W[w][0], ww1 = d_W[w][1], ww2 = d_W[w][2], ww3 = d_W[w][3];
    for (int dd = 0; dd < 48; dd++) {
        const int dp = t0 - 7 + dd;
        float v = 0.0f;
        if (dp >= 0 && dp < 128) {
            const float* a2 = &A2h[dp * 12 + c];
            float acc = 0.0f;
            acc = fmaf(ww0, a2[0], acc);
            acc = fmaf(ww1, a2[3], acc);
            acc = fmaf(ww2, a2[6], acc);
            acc = fmaf(ww3, a2[9], acc);
            v = acc;
        }
        B1s[dd * 384 + t] = v;
    }
    __syncthreads();

    float g[16];
#pragma unroll
    for (int j = 0; j < 16; j++) g[j] = d_G[j];

    for (int dl = 0; dl < 32; dl++) {
        float acc = 0.0f;
#pragma unroll
        for (int j = 0; j < 16; j++)
            acc = fmaf(g[j], B1s[(dl + j) * 384 + t], acc);
        const int d = t0 + dl;
        d_F2[(((size_t)b * 128 + d) * 128 + h) * 384 + t] = acc;
    }
}

// ---------------- convH ----------------
// grid (4, 128, 2) = (h-tile, d, b); 384 threads
__global__ __launch_bounds__(384) void flowH_kernel() {
    float* S = dyn_smem;                    // [48][384]
    const int t = threadIdx.x;
    const int t0 = blockIdx.x * 32;
    const int d = blockIdx.y, b = blockIdx.z;
    const size_t base = ((size_t)b * 128 + d) * 128;

    for (int dd = 0; dd < 48; dd++) {
        const int hp = t0 - 7 + dd;
        S[dd * 384 + t] = (hp >= 0 && hp < 128) ? d_F2[(base + hp) * 384 + t] : 0.0f;
    }
    __syncthreads();

    float g[16];
#pragma unroll
    for (int j = 0; j < 16; j++) g[j] = d_G[j];

    for (int hl = 0; hl < 32; hl++) {
        float acc = 0.0f;
#pragma unroll
        for (int j = 0; j < 16; j++)
            acc = fmaf(g[j], S[(hl + j) * 384 + t], acc);
        d_F3[(base + t0 + hl) * 384 + t] = acc;
    }
}

// ---------------- convW + warp (image trilinear + label nearest) ----------------
__device__ __forceinline__ float4 lerp4(float4 p, float4 q, float t) {
    float4 r;
    r.x = fmaf(t, q.x - p.x, p.x);
    r.y = fmaf(t, q.y - p.y, p.y);
    r.z = fmaf(t, q.z - p.z, p.z);
    r.w = fmaf(t, q.w - p.w, p.w);
    return r;
}

// grid (32, 128, 2) = (h-quad, d, b); 512 threads = 4 h-pencils x 128 w
__global__ __launch_bounds__(512) void warp_kernel(
    const float* __restrict__ img, const int* __restrict__ lab, float* __restrict__ out)
{
    __shared__ float fl3[4 * 384];
    const int t = threadIdx.x;
    const int d = blockIdx.y, b = blockIdx.z;
    const size_t fbase = (((size_t)b * 128 + d) * 128 + blockIdx.x * 4) * 384;

    for (int i = t; i < 1536; i += 512) fl3[i] = d_F3[fbase + i];
    __syncthreads();

    const int hl = t >> 7, w = t & 127;
    const int h = blockIdx.x * 4 + hl;

    float g[16];
#pragma unroll
    for (int j = 0; j < 16; j++) g[j] = d_G[j];

    // convW (zero-pad == tap-skip, bit-exact), then *35 (rounded), then grid+flow (rounded)
    float fc[3];
#pragma unroll
    for (int c = 0; c < 3; c++) {
        float acc = 0.0f;
#pragma unroll
        for (int j = 0; j < 16; j++) {
            const int s = w + j - 7;
            const float v = (s >= 0 && s < 128) ? fl3[hl * 384 + s * 3 + c] : 0.0f;
            acc = fmaf(g[j], v, acc);
        }
        fc[c] = acc;
    }

    const float wd = __fadd_rn((float)d, __fmul_rn(fc[0], 35.0f));
    const float wh = __fadd_rn((float)h, __fmul_rn(fc[1], 35.0f));
    const float ww = __fadd_rn((float)w, __fmul_rn(fc[2], 35.0f));

    const float fld = floorf(wd), flh = floorf(wh), flw = floorf(ww);
    const float td = wd - fld, th = wh - flh, tw = ww - flw;

    const int id = (int)fld, ih = (int)flh, iw = (int)flw;
    const int d0 = min(max(id,     0), 127), d1 = min(max(id + 1, 0), 127);
    const int h0 = min(max(ih,     0), 127), h1 = min(max(ih + 1, 0), 127);
    const int w0 = min(max(iw,     0), 127), w1 = min(max(iw + 1, 0), 127);

    const float4* __restrict__ I = reinterpret_cast<const float4*>(img);
    const int bbase = b << 21;

    const int r00 = bbase + (d0 * 128 + h0) * 128;
    const int r01 = bbase + (d0 * 128 + h1) * 128;
    const int r10 = bbase + (d1 * 128 + h0) * 128;
    const int r11 = bbase + (d1 * 128 + h1) * 128;

    const float4 a000 = I[r00 + w0], a001 = I[r00 + w1];
    const float4 a010 = I[r01 + w0], a011 = I[r01 + w1];
    const float4 a100 = I[r10 + w0], a101 = I[r10 + w1];
    const float4 a110 = I[r11 + w0], a111 = I[r11 + w1];

    const float4 c00 = lerp4(a000, a001, tw);
    const float4 c01 = lerp4(a010, a011, tw);
    const float4 c10 = lerp4(a100, a101, tw);
    const float4 c11 = lerp4(a110, a111, tw);
    const float4 c0  = lerp4(c00, c01, th);
    const float4 c1  = lerp4(c10, c11, th);

    const int oidx = bbase + (d * 128 + h) * 128 + w;
    reinterpret_cast<float4*>(out)[oidx] = lerp4(c0, c1, td);

    const int nd = min(max((int)rintf(wd), 0), 127);
    const int nh = min(max((int)rintf(wh), 0), 127);
    const int nw = min(max((int)rintf(ww), 0), 127);
    out[IMG_ELEMS + oidx] = (float)__ldg(&lab[bbase + (nd * 128 + nh) * 128 + nw]);
}

extern "C" void kernel_launch(void* const* d_in, const int* in_sizes, int n_in,
                              void* d_out, int out_size) {
    const float* img    = (const float*)d_in[0];
    const int*   lab    = (const int*)  d_in[1];
    const float* coarse = (const float*)d_in[2];
    float* out = (float*)d_out;

    const int win_smem = 48 * 384 * (int)sizeof(float); // 73728 B
    static int attr_done = 0;
    if (!attr_done) {
        cudaFuncSetAttribute(flowD_kernel, cudaFuncAttributeMaxDynamicSharedMemorySize, win_smem);
        cudaFuncSetAttribute(flowH_kernel, cudaFuncAttributeMaxDynamicSharedMemorySize, win_smem);
        attr_done = 1;
    }

    init_weights_kernel<<<1, 128>>>();
    flowD_kernel<<<dim3(4, 128, 2), 384, win_smem>>>(coarse);
    flowH_kernel<<<dim3(4, 128, 2), 384, win_smem>>>();
    warp_kernel<<<dim3(32, 128, 2), 512>>>(img, lab, out);
}

// round 5
// speedup vs baseline: 1.4816x; 1.0007x over previous
#include <cuda_runtime.h>
#include <math.h>

// B=2, D=H=W=128, C=4 image; label int32 C=1; coarse flow [2,4,4,4,3].
// Output: image [2,128,128,128,4] f32 then label [2,128,128,128] (as float).

#define NVOX      (2*128*128*128)
#define IMG_ELEMS (NVOX*4)
#define FLOW_N    (NVOX*3)

__device__ float d_W[128][4];   // fp32 resize weights (jax-faithful rounding)
__device__ float d_G[16];       // fp32 gaussian taps (float64 -> f32, numpy-faithful)
__device__ float d_F2[FLOW_N];  // flow after resize + convD   [b][d][h][w*3+c]
__device__ float d_F3[FLOW_N];  // flow after convH + convW    [b][d][h][w*3+c]

// ---------------- stage 0: weights (exact op structure jax/numpy use) ----------------
__device__ __forceinline__ float keys_f32(float x) {
    if (x < 1.0f) {
        float t = __fadd_rn(__fmul_rn(1.5f, x), -2.5f);
        t = __fmul_rn(t, x); t = __fmul_rn(t, x);
        return __fadd_rn(t, 1.0f);
    }
    if (x < 2.0f) {
        float t = __fadd_rn(__fmul_rn(-0.5f, x), 2.5f);
        t = __fadd_rn(__fmul_rn(t, x), -4.0f);
        t = __fmul_rn(t, x);
        return __fadd_rn(t, 2.0f);
    }
    return 0.0f;
}

__global__ void init_weights_kernel() {
    int x = threadIdx.x; // 0..127
    float s = __fadd_rn(__fdiv_rn(__fadd_rn((float)x, 0.5f), 32.0f), -0.5f);
    float wv[4];
#pragma unroll
    for (int a = 0; a < 4; a++) wv[a] = keys_f32(fabsf(__fadd_rn(s, -(float)a)));
    float tot = __fadd_rn(__fadd_rn(__fadd_rn(wv[0], wv[1]), wv[2]), wv[3]);
#pragma unroll
    for (int a = 0; a < 4; a++) d_W[x][a] = __fdiv_rn(wv[a], tot);

    if (x < 16) {
        double gs = 0.0;
        for (int j = 0; j < 16; j++) { double o = (double)(j - 7); gs += exp(-o * o / 12.5); }
        double o = (double)(x - 7);
        d_G[x] = (float)(exp(-o * o / 12.5) / gs);
    }
}

// ---------------- fused resizeD+resizeH+resizeW+convD (sliding-window conv) ----------------
// grid (4, 128, 2) = (d-tile of 32, h, b); 384 threads (wc = w*3+c)
__global__ __launch_bounds__(384) void flowD_kernel(const float* __restrict__ coarse) {
    __shared__ float cf[192];
    __shared__ float A2h[128 * 12];   // [d'][e*3+c]
    const int t = threadIdx.x;
    const int t0 = blockIdx.x * 32;
    const int h = blockIdx.y, b = blockIdx.z;

    if (t < 192) cf[t] = coarse[b * 192 + t];
    __syncthreads();

    // A2h[d'][ec] = sum_bb W[h][bb] * (sum_a W[d'][a] * cf[a][bb][ec])   (same fma order as staged)
    const float wh0 = d_W[h][0], wh1 = d_W[h][1], wh2 = d_W[h][2], wh3 = d_W[h][3];
    for (int i = t; i < 1536; i += 384) {
        const int dp = i / 12, ec = i - dp * 12;
        float acc = 0.0f;
#pragma unroll
        for (int bb = 0; bb < 4; bb++) {
            float a1 = 0.0f;
#pragma unroll
            for (int a = 0; a < 4; a++)
                a1 = fmaf(d_W[dp][a], cf[a * 48 + bb * 12 + ec], a1);
            const float whb = (bb == 0) ? wh0 : (bb == 1) ? wh1 : (bb == 2) ? wh2 : wh3;
            acc = fmaf(whb, a1, acc);
        }
        A2h[i] = acc;
    }
    __syncthreads();

    const int w = t / 3, c = t - 3 * w;
    const float ww0 = d_W[w][0], ww1 = d_W[w][1], ww2 = d_W[w][2], ww3 = d_W[w][3];

    // b1(dp) = resizeW output at (dp, h, w, c); zero outside [0,128) (bit-exact to tap skip)
    auto b1 = [&](int dp) -> float {
        if (dp < 0 || dp >= 128) return 0.0f;
        const float* a2 = &A2h[dp * 12 + c];
        float acc = 0.0f;
        acc = fmaf(ww0, a2[0], acc);
        acc = fmaf(ww1, a2[3], acc);
        acc = fmaf(ww2, a2[6], acc);
        acc = fmaf(ww3, a2[9], acc);
        return acc;
    };

    float g[16];
#pragma unroll
    for (int j = 0; j < 16; j++) g[j] = d_G[j];

    float win[16];
#pragma unroll
    for (int j = 0; j < 16; j++) win[j] = b1(t0 - 7 + j);

    const size_t rowstride = 128 * 384;
    size_t obase = (((size_t)b * 128 + t0) * 128 + h) * 384 + t;
#pragma unroll
    for (int dl = 0; dl < 32; dl++) {
        float acc = 0.0f;
#pragma unroll
        for (int j = 0; j < 16; j++)
            acc = fmaf(g[j], win[(dl + j) & 15], acc);   // j ascending: bit-exact
        d_F2[obase] = acc;
        obase += rowstride;
        if (dl < 31) win[dl & 15] = b1(t0 - 7 + dl + 16);
    }
}

// ---------------- fused convH + convW (both sliding-window) ----------------
// grid (8, 128, 2) = (h-tile of 16, d, b); 384 threads
extern __shared__ float dyn_smem[];
__global__ __launch_bounds__(384) void flowHW_kernel() {
    float* W31 = dyn_smem;            // [31][384] input h-window, later reused for output
    float* H16 = dyn_smem + 31 * 384; // [16][384] convH results
    const int t = threadIdx.x;
    const int h0 = blockIdx.x * 16;
    const int d = blockIdx.y, b = blockIdx.z;
    const size_t base = ((size_t)b * 128 + d) * 128;

    // phase 1: load h-window rows h0-7 .. h0+23 (zero-pad outside)
    for (int r = 0; r < 31; r++) {
        const int hp = h0 - 7 + r;
        W31[r * 384 + t] = (hp >= 0 && hp < 128) ? d_F2[(base + hp) * 384 + t] : 0.0f;
    }
    __syncthreads();

    float g[16];
#pragma unroll
    for (int j = 0; j < 16; j++) g[j] = d_G[j];

    // phase 2: convH, sliding window along hl
    {
        float win[16];
#pragma unroll
        for (int j = 0; j < 16; j++) win[j] = W31[j * 384 + t];
#pragma unroll
        for (int hl = 0; hl < 16; hl++) {
            float acc = 0.0f;
#pragma unroll
            for (int j = 0; j < 16; j++)
                acc = fmaf(g[j], win[(hl + j) & 15], acc);
            H16[hl * 384 + t] = acc;
            if (hl < 15) win[hl & 15] = W31[(hl + 16) * 384 + t];
        }
    }
    __syncthreads();

    // phase 3: convW, remapped: 48 pencils (h',c) x 8 w-chunks of 16; sliding window along w
    {
        const int p = t >> 3, q = t & 7;       // p: 0..47, q: 0..7
        const int hh = p / 3, c = p - 3 * hh;  // pencil
        const int s0 = q * 16 - 7;
        auto hv = [&](int s) -> float {
            return (s >= 0 && s < 128) ? H16[hh * 384 + s * 3 + c] : 0.0f;
        };
        float win[16];
#pragma unroll
        for (int j = 0; j < 16; j++) win[j] = hv(s0 + j);
#pragma unroll
        for (int wl = 0; wl < 16; wl++) {
            float acc = 0.0f;
#pragma unroll
            for (int j = 0; j < 16; j++)
                acc = fmaf(g[j], win[(wl + j) & 15], acc);
            W31[hh * 384 + (q * 16 + wl) * 3 + c] = acc;  // reuse W31 as output tile
            if (wl < 15) win[wl & 15] = hv(s0 + wl + 16);
        }
    }
    __syncthreads();

    // phase 4: coalesced store of the 16 finished rows
    for (int r = 0; r < 16; r++)
        d_F3[(base + h0 + r) * 384 + t] = W31[r * 384 + t];
}

// ---------------- warp: image trilinear + label nearest ----------------
__device__ __forceinline__ float4 lerp4(float4 p, float4 q, float t) {
    float4 r;
    r.x = fmaf(t, q.x - p.x, p.x);
    r.y = fmaf(t, q.y - p.y, p.y);
    r.z = fmaf(t, q.z - p.z, p.z);
    r.w = fmaf(t, q.w - p.w, p.w);
    return r;
}

// grid (32, 128, 2) = (h-quad, d, b); 512 threads = 4 h-pencils x 128 w
__global__ __launch_bounds__(512) void warp_kernel(
    const float* __restrict__ img, const int* __restrict__ lab, float* __restrict__ out)
{
    __shared__ float fl3[4 * 384];
    const int t = threadIdx.x;
    const int d = blockIdx.y, b = blockIdx.z;
    const size_t fbase = (((size_t)b * 128 + d) * 128 + blockIdx.x * 4) * 384;

    for (int i = t; i < 1536; i += 512) fl3[i] = d_F3[fbase + i];
    __syncthreads();

    const int hl = t >> 7, w = t & 127;
    const int h = blockIdx.x * 4 + hl;

    const float f0 = fl3[hl * 384 + w * 3 + 0];
    const float f1 = fl3[hl * 384 + w * 3 + 1];
    const float f2 = fl3[hl * 384 + w * 3 + 2];

    const float wd = __fadd_rn((float)d, __fmul_rn(f0, 35.0f));
    const float wh = __fadd_rn((float)h, __fmul_rn(f1, 35.0f));
    const float ww = __fadd_rn((float)w, __fmul_rn(f2, 35.0f));

    const float fld = floorf(wd), flh = floorf(wh), flw = floorf(ww);
    const float td = wd - fld, th = wh - flh, tw = ww - flw;

    const int id = (int)fld, ih = (int)flh, iw = (int)flw;
    const int d0 = min(max(id,     0), 127), d1 = min(max(id + 1, 0), 127);
    const int h0 = min(max(ih,     0), 127), h1 = min(max(ih + 1, 0), 127);
    const int w0 = min(max(iw,     0), 127), w1 = min(max(iw + 1, 0), 127);

    const float4* __restrict__ I = reinterpret_cast<const float4*>(img);
    const int bbase = b << 21;

    const int r00 = bbase + (d0 * 128 + h0) * 128;
    const int r01 = bbase + (d0 * 128 + h1) * 128;
    const int r10 = bbase + (d1 * 128 + h0) * 128;
    const int r11 = bbase + (d1 * 128 + h1) * 128;

    const float4 a000 = I[r00 + w0], a001 = I[r00 + w1];
    const float4 a010 = I[r01 + w0], a011 = I[r01 + w1];
    const float4 a100 = I[r10 + w0], a101 = I[r10 + w1];
    const float4 a110 = I[r11 + w0], a111 = I[r11 + w1];

    const float4 c00 = lerp4(a000, a001, tw);
    const float4 c01 = lerp4(a010, a011, tw);
    const float4 c10 = lerp4(a100, a101, tw);
    const float4 c11 = lerp4(a110, a111, tw);
    const float4 c0  = lerp4(c00, c01, th);
    const float4 c1  = lerp4(c10, c11, th);

    const int oidx = bbase + (d * 128 + h) * 128 + w;
    reinterpret_cast<float4*>(out)[oidx] = lerp4(c0, c1, td);

    const int nd = min(max((int)rintf(wd), 0), 127);
    const int nh = min(max((int)rintf(wh), 0), 127);
    const int nw = min(max((int)rintf(ww), 0), 127);
    out[IMG_ELEMS + oidx] = (float)__ldg(&lab[bbase + (nd * 128 + nh) * 128 + nw]);
}

extern "C" void kernel_launch(void* const* d_in, const int* in_sizes, int n_in,
                              void* d_out, int out_size) {
    const float* img    = (const float*)d_in[0];
    const int*   lab    = (const int*)  d_in[1];
    const float* coarse = (const float*)d_in[2];
    float* out = (float*)d_out;

    const int hw_smem = 47 * 384 * (int)sizeof(float); // 72192 B
    static int attr_done = 0;
    if (!attr_done) {
        cudaFuncSetAttribute(flowHW_kernel, cudaFuncAttributeMaxDynamicSharedMemorySize, hw_smem);
        attr_done = 1;
    }

    init_weights_kernel<<<1, 128>>>();
    flowD_kernel<<<dim3(4, 128, 2), 384>>>(coarse);
    flowHW_kernel<<<dim3(8, 128, 2), 384, hw_smem>>>();
    warp_kernel<<<dim3(32, 128, 2), 512>>>(img, lab, out);
}

// round 6
// speedup vs baseline: 1.5673x; 1.0579x over previous
#include <cuda_runtime.h>
#include <math.h>

// B=2, D=H=W=128, C=4 image; label int32 C=1; coarse flow [2,4,4,4,3].
// Output: image [2,128,128,128,4] f32 then label [2,128,128,128] (as float).
// Flow fields stored PLANAR: [c][b][d][h][w]  (c=0,1,2)

#define NVOX      (2*128*128*128)
#define IMG_ELEMS (NVOX*4)
#define FLOW_N    (NVOX*3)

__device__ float d_F2[FLOW_N];  // after resize + convD, planar
__device__ float d_F3[FLOW_N];  // after convH + convW,   planar

// ---- weight generation (exact op structure jax/numpy use; identical in every kernel) ----
__device__ __forceinline__ float keys_f32(float x) {
    if (x < 1.0f) {
        float t = __fadd_rn(__fmul_rn(1.5f, x), -2.5f);
        t = __fmul_rn(t, x); t = __fmul_rn(t, x);
        return __fadd_rn(t, 1.0f);
    }
    if (x < 2.0f) {
        float t = __fadd_rn(__fmul_rn(-0.5f, x), 2.5f);
        t = __fadd_rn(__fmul_rn(t, x), -4.0f);
        t = __fmul_rn(t, x);
        return __fadd_rn(t, 2.0f);
    }
    return 0.0f;
}

// threads t<128 fill Ws[128][4]; t in [128,144) seed gtmp; caller syncs, then t<16 fill Gs.
__device__ __forceinline__ void gen_W_row(float* Wrow, int x) {
    float s = __fadd_rn(__fdiv_rn(__fadd_rn((float)x, 0.5f), 32.0f), -0.5f);
    float wv[4];
#pragma unroll
    for (int a = 0; a < 4; a++) wv[a] = keys_f32(fabsf(__fadd_rn(s, -(float)a)));
    float tot = __fadd_rn(__fadd_rn(__fadd_rn(wv[0], wv[1]), wv[2]), wv[3]);
#pragma unroll
    for (int a = 0; a < 4; a++) Wrow[a] = __fdiv_rn(wv[a], tot);
}

// ---------------- fused resizeD+resizeH+resizeW+convD (planar out) ----------------
// grid (4, 128, 2) = (d-tile of 32, h, b); 384 threads, planar mapping (c = t>>7, w = t&127)
__global__ __launch_bounds__(384) void flowD_kernel(const float* __restrict__ coarse) {
    __shared__ float  cf[192];
    __shared__ float  A2h[1536];     // [d'][e*3+c]
    __shared__ float  Ws[128][4];
    __shared__ float  Gs[16];
    __shared__ double gtmp[16];
    const int t = threadIdx.x;
    const int t0 = blockIdx.x * 32;
    const int h = blockIdx.y, b = blockIdx.z;

    if (t < 128) gen_W_row(Ws[t], t);
    if (t >= 128 && t < 144) { double o = (double)(t - 128 - 7); gtmp[t - 128] = exp(-o * o / 12.5); }
    if (t >= 192 && t < 384) cf[t - 192] = coarse[b * 192 + (t - 192)];
    __syncthreads();
    if (t < 16) {
        double gs = 0.0;
        for (int j = 0; j < 16; j++) gs += gtmp[j];
        Gs[t] = (float)(gtmp[t] / gs);
    }
    __syncthreads();

    // A2h[d'][ec] = sum_bb W[h][bb] * (sum_a W[d'][a] * cf[a][bb][ec])   (frozen fma order)
    const float wh0 = Ws[h][0], wh1 = Ws[h][1], wh2 = Ws[h][2], wh3 = Ws[h][3];
    for (int i = t; i < 1536; i += 384) {
        const int dp = i / 12, ec = i - dp * 12;
        float acc = 0.0f;
#pragma unroll
        for (int bb = 0; bb < 4; bb++) {
            float a1 = 0.0f;
#pragma unroll
            for (int a = 0; a < 4; a++)
                a1 = fmaf(Ws[dp][a], cf[a * 48 + bb * 12 + ec], a1);
            const float whb = (bb == 0) ? wh0 : (bb == 1) ? wh1 : (bb == 2) ? wh2 : wh3;
            acc = fmaf(whb, a1, acc);
        }
        A2h[i] = acc;
    }
    __syncthreads();

    const int c = t >> 7, w = t & 127;
    const float ww0 = Ws[w][0], ww1 = Ws[w][1], ww2 = Ws[w][2], ww3 = Ws[w][3];

    auto b1 = [&](int dp) -> float {   // zero outside [0,128) == tap-skip, bit-exact
        if (dp < 0 || dp >= 128) return 0.0f;
        const float* a2 = &A2h[dp * 12 + c];
        float acc = 0.0f;
        acc = fmaf(ww0, a2[0], acc);
        acc = fmaf(ww1, a2[3], acc);
        acc = fmaf(ww2, a2[6], acc);
        acc = fmaf(ww3, a2[9], acc);
        return acc;
    };

    float g[16];
#pragma unroll
    for (int j = 0; j < 16; j++) g[j] = Gs[j];

    float win[16];
#pragma unroll
    for (int j = 0; j < 16; j++) win[j] = b1(t0 - 7 + j);

    size_t obase = ((size_t)(c * 2 + b) << 21) + ((size_t)t0 << 14) + (h << 7) + w;
#pragma unroll
    for (int dl = 0; dl < 32; dl++) {
        float acc = 0.0f;
#pragma unroll
        for (int j = 0; j < 16; j++)
            acc = fmaf(g[j], win[(dl + j) & 15], acc);   // j ascending: bit-exact
        d_F2[obase] = acc;
        obase += 16384;
        if (dl < 31) win[dl & 15] = b1(t0 - 7 + dl + 16);
    }
}

// ---------------- fused convH + convW (planar, conflict-free sliding windows) ----------------
// grid (8, 128, 2) = (h-tile of 16, d, b); 384 threads
// dyn smem: IN [3][31][128] = 11904 floats; H [48][129] = 6192 floats at offset 11904.
// OUT reuses IN region as [48][129].
extern __shared__ float dyn_smem[];
__global__ __launch_bounds__(384) void flowHW_kernel() {
    float* IN = dyn_smem;
    float* H  = dyn_smem + 11904;
    float* OUT = dyn_smem;
    __shared__ float  Gs[16];
    __shared__ double gtmp[16];
    const int t = threadIdx.x;
    const int h0 = blockIdx.x * 16;
    const int d = blockIdx.y, b = blockIdx.z;

    if (t < 16) { double o = (double)(t - 7); gtmp[t] = exp(-o * o / 12.5); }
    __syncthreads();
    if (t < 16) {
        double gs = 0.0;
        for (int j = 0; j < 16; j++) gs += gtmp[j];
        Gs[t] = (float)(gtmp[t] / gs);
    }

    // phase 1: load 3 planes x 31 h-rows (zero-pad outside)
    for (int i = t; i < 3 * 31 * 128; i += 384) {
        const int c = i / 3968, rem = i - c * 3968, r = rem >> 7, w = rem & 127;
        const int hp = h0 - 7 + r;
        IN[i] = (hp >= 0 && hp < 128)
              ? d_F2[((size_t)(c * 2 + b) << 21) + ((size_t)d << 14) + (hp << 7) + w] : 0.0f;
    }
    __syncthreads();

    float g[16];
#pragma unroll
    for (int j = 0; j < 16; j++) g[j] = Gs[j];

    // phase 2: convH, sliding along h. thread = (c = t>>7, w = t&127)
    {
        const int c = t >> 7, w = t & 127;
        const float* col = IN + c * 3968 + w;
        float win[16];
#pragma unroll
        for (int j = 0; j < 16; j++) win[j] = col[j << 7];
#pragma unroll
        for (int hl = 0; hl < 16; hl++) {
            float acc = 0.0f;
#pragma unroll
            for (int j = 0; j < 16; j++)
                acc = fmaf(g[j], win[(hl + j) & 15], acc);
            H[(c * 16 + hl) * 129 + w] = acc;
            if (hl < 15) win[hl & 15] = col[(hl + 16) << 7];
        }
    }
    __syncthreads();

    // phase 3: convW, sliding along w. chunk-major: t = q*48 + pi (pi = c*16+hl), stride-129 rows
    {
        const int q = t / 48, pi = t - q * 48;
        const int s0 = q * 16 - 7;
        const float* row = H + pi * 129;
        auto hv = [&](int s) -> float { return (s >= 0 && s < 128) ? row[s] : 0.0f; };
        float win[16];
#pragma unroll
        for (int j = 0; j < 16; j++) win[j] = hv(s0 + j);
        float* orow = OUT + pi * 129 + q * 16;
#pragma unroll
        for (int wl = 0; wl < 16; wl++) {
            float acc = 0.0f;
#pragma unroll
            for (int j = 0; j < 16; j++)
                acc = fmaf(g[j], win[(wl + j) & 15], acc);
            orow[wl] = acc;
            if (wl < 15) win[wl & 15] = hv(s0 + wl + 16);
        }
    }
    __syncthreads();

    // phase 4: coalesced planar store
    {
        const int c = t >> 7, w = t & 127;
        const size_t gbase = ((size_t)(c * 2 + b) << 21) + ((size_t)d << 14) + w;
#pragma unroll
        for (int hl = 0; hl < 16; hl++)
            d_F3[gbase + ((h0 + hl) << 7)] = OUT[(c * 16 + hl) * 129 + w];
    }
}

// ---------------- warp: image trilinear + label nearest ----------------
__device__ __forceinline__ float4 lerp4(float4 p, float4 q, float t) {
    float4 r;
    r.x = fmaf(t, q.x - p.x, p.x);
    r.y = fmaf(t, q.y - p.y, p.y);
    r.z = fmaf(t, q.z - p.z, p.z);
    r.w = fmaf(t, q.w - p.w, p.w);
    return r;
}

// grid (32, 128, 2) = (h-quad, d, b); 512 threads = 4 h-pencils x 128 w
__global__ __launch_bounds__(512) void warp_kernel(
    const float* __restrict__ img, const int* __restrict__ lab, float* __restrict__ out)
{
    __shared__ float fl[3 * 4 * 128];   // [c][hl][w]
    const int t = threadIdx.x;
    const int d = blockIdx.y, b = blockIdx.z;

    for (int i = t; i < 1536; i += 512) {
        const int c = i >> 9, rem = i & 511, hl2 = rem >> 7, w2 = rem & 127;
        fl[i] = d_F3[((size_t)(c * 2 + b) << 21) + ((size_t)d << 14) + ((blockIdx.x * 4 + hl2) << 7) + w2];
    }
    __syncthreads();

    const int hl = t >> 7, w = t & 127;
    const int h = blockIdx.x * 4 + hl;

    const float f0 = fl[          hl * 128 + w];
    const float f1 = fl[ 512 +    hl * 128 + w];
    const float f2 = fl[1024 +    hl * 128 + w];

    const float wd = __fadd_rn((float)d, __fmul_rn(f0, 35.0f));
    const float wh = __fadd_rn((float)h, __fmul_rn(f1, 35.0f));
    const float ww = __fadd_rn((float)w, __fmul_rn(f2, 35.0f));

    const float fld = floorf(wd), flh = floorf(wh), flw = floorf(ww);
    const float td = wd - fld, th = wh - flh, tw = ww - flw;

    const int id = (int)fld, ih = (int)flh, iw = (int)flw;
    const int d0 = min(max(id,     0), 127), d1 = min(max(id + 1, 0), 127);
    const int h0 = min(max(ih,     0), 127), h1 = min(max(ih + 1, 0), 127);
    const int w0 = min(max(iw,     0), 127), w1 = min(max(iw + 1, 0), 127);

    const float4* __restrict__ I = reinterpret_cast<const float4*>(img);
    const int bbase = b << 21;

    const int r00 = bbase + (d0 * 128 + h0) * 128;
    const int r01 = bbase + (d0 * 128 + h1) * 128;
    const int r10 = bbase + (d1 * 128 + h0) * 128;
    const int r11 = bbase + (d1 * 128 + h1) * 128;

    const float4 a000 = I[r00 + w0], a001 = I[r00 + w1];
    const float4 a010 = I[r01 + w0], a011 = I[r01 + w1];
    const float4 a100 = I[r10 + w0], a101 = I[r10 + w1];
    const float4 a110 = I[r11 + w0], a111 = I[r11 + w1];

    const float4 c00 = lerp4(a000, a001, tw);
    const float4 c01 = lerp4(a010, a011, tw);
    const float4 c10 = lerp4(a100, a101, tw);
    const float4 c11 = lerp4(a110, a111, tw);
    const float4 c0  = lerp4(c00, c01, th);
    const float4 c1  = lerp4(c10, c11, th);

    const int oidx = bbase + (d * 128 + h) * 128 + w;
    reinterpret_cast<float4*>(out)[oidx] = lerp4(c0, c1, td);

    const int nd = min(max((int)rintf(wd), 0), 127);
    const int nh = min(max((int)rintf(wh), 0), 127);
    const int nw = min(max((int)rintf(ww), 0), 127);
    out[IMG_ELEMS + oidx] = (float)__ldg(&lab[bbase + (nd * 128 + nh) * 128 + nw]);
}

extern "C" void kernel_launch(void* const* d_in, const int* in_sizes, int n_in,
                              void* d_out, int out_size) {
    const float* img    = (const float*)d_in[0];
    const int*   lab    = (const int*)  d_in[1];
    const float* coarse = (const float*)d_in[2];
    float* out = (float*)d_out;

    const int hw_smem = (11904 + 6192) * (int)sizeof(float); // 72384 B
    static int attr_done = 0;
    if (!attr_done) {
        cudaFuncSetAttribute(flowHW_kernel, cudaFuncAttributeMaxDynamicSharedMemorySize, hw_smem);
        attr_done = 1;
    }

    flowD_kernel<<<dim3(4, 128, 2), 384>>>(coarse);
    flowHW_kernel<<<dim3(8, 128, 2), 384, hw_smem>>>();
    warp_kernel<<<dim3(32, 128, 2), 512>>>(img, lab, out);
}